// round 3
// baseline (speedup 1.0000x reference)
#include <cuda_runtime.h>
#include <math.h>

#define EMBED 1024
#define QKVN  1536
#define INNER 512
#define NHEAD 8
#define HDIM  64
#define BATCH 2
#define SEQ   4096
#define MROWS (BATCH * SEQ)   // 8192

// Scratch (allocation-free rule: __device__ globals)
__device__ float g_q[BATCH * NHEAD * SEQ * HDIM];   // 16.8 MB, [B,H,N,D], pre-scaled by 0.125
__device__ float g_k[BATCH * NHEAD * SEQ * HDIM];
__device__ float g_v[BATCH * NHEAD * SEQ * HDIM];
__device__ float g_ao[MROWS * INNER];               // attention out, [B,N,H*D] row-major

// ---------------------------------------------------------------------------
// Kernel 1: QKV projection  C = X @ Wqkv + b, scattered to Q/K/V [B,H,N,D]
// BM=128, BN=128, BK=16, 8x8 micro-tile, 256 threads
// ---------------------------------------------------------------------------
__global__ __launch_bounds__(256, 2) void qkv_gemm_kernel(
    const float* __restrict__ A,     // [8192, 1024]
    const float* __restrict__ W,     // [1024, 1536]
    const float* __restrict__ bias)  // [1536]
{
    __shared__ float As[16][128];
    __shared__ float Bs[16][128];
    const int tid  = threadIdx.x;
    const int tx   = tid & 15, ty = tid >> 4;
    const int row0 = blockIdx.y * 128;
    const int col0 = blockIdx.x * 128;

    float acc[8][8];
    #pragma unroll
    for (int i = 0; i < 8; i++)
        #pragma unroll
        for (int j = 0; j < 8; j++) acc[i][j] = 0.f;

    for (int kt = 0; kt < EMBED; kt += 16) {
        #pragma unroll
        for (int it = 0; it < 2; it++) {
            int f = tid + it * 256;
            int r = f >> 2, c4 = (f & 3) * 4;
            float4 v = *(const float4*)&A[(size_t)(row0 + r) * EMBED + kt + c4];
            As[c4 + 0][r] = v.x; As[c4 + 1][r] = v.y;
            As[c4 + 2][r] = v.z; As[c4 + 3][r] = v.w;
        }
        #pragma unroll
        for (int it = 0; it < 2; it++) {
            int f = tid + it * 256;
            int r = f >> 5, c4 = (f & 31) * 4;
            *(float4*)&Bs[r][c4] = *(const float4*)&W[(size_t)(kt + r) * QKVN + col0 + c4];
        }
        __syncthreads();
        #pragma unroll
        for (int k = 0; k < 16; k++) {
            float a[8], b[8];
            *(float4*)&a[0] = *(float4*)&As[k][ty * 8];
            *(float4*)&a[4] = *(float4*)&As[k][ty * 8 + 4];
            *(float4*)&b[0] = *(float4*)&Bs[k][tx * 8];
            *(float4*)&b[4] = *(float4*)&Bs[k][tx * 8 + 4];
            #pragma unroll
            for (int i = 0; i < 8; i++)
                #pragma unroll
                for (int j = 0; j < 8; j++)
                    acc[i][j] = fmaf(a[i], b[j], acc[i][j]);
        }
        __syncthreads();
    }

    // Epilogue: bias + scatter to [B,H,N,D]; fold softmax scale into Q
    #pragma unroll
    for (int i = 0; i < 8; i++) {
        int m  = row0 + ty * 8 + i;
        int bb = m >> 12;            // /4096
        int n  = m & (SEQ - 1);
        #pragma unroll
        for (int j = 0; j < 8; j++) {
            int o = col0 + tx * 8 + j;
            float val = acc[i][j] + bias[o];
            int part  = o >> 9;      // 0=q,1=k,2=v
            int inner = o & 511;
            int h = inner >> 6, d = inner & 63;
            size_t idx = (((size_t)(bb * NHEAD + h)) * SEQ + n) * HDIM + d;
            if (part == 0)      g_q[idx] = val * 0.125f;   // 1/sqrt(64)
            else if (part == 1) g_k[idx] = val;
            else                g_v[idx] = val;
        }
    }
}

// ---------------------------------------------------------------------------
// Kernel 2: flash attention, Br=Bc=64, D=64, 256 threads (16x16 grid)
// Thread (tx,ty) owns rows ty*4+i, cols tx+16*j (interleaved -> conflict-free LDS)
// ---------------------------------------------------------------------------
#define KS_STRIDE 68
#define ATTN_SMEM_BYTES ((64 * 64 * 3 + 64 * KS_STRIDE) * 4)   // 66560

__global__ __launch_bounds__(256, 2) void attn_kernel()
{
    extern __shared__ float sm[];
    float* Qs = sm;                       // 64 x 64
    float* Ks = sm + 64 * 64;             // 64 x 68 (padded: conflict-free b-loads)
    float* Vs = Ks + 64 * KS_STRIDE;      // 64 x 64
    float* Ps = Vs + 64 * 64;             // 64 x 64

    const int tid = threadIdx.x;
    const int tx  = tid & 15, ty = tid >> 4;
    const int bh  = blockIdx.y;           // b*8 + h
    const int q0  = blockIdx.x * 64;

    const float* Qg = g_q + ((size_t)bh * SEQ + q0) * HDIM;
    const float* Kg = g_k + (size_t)bh * SEQ * HDIM;
    const float* Vg = g_v + (size_t)bh * SEQ * HDIM;

    #pragma unroll
    for (int it = 0; it < 4; it++) {
        int f = tid + it * 256;
        int r = f >> 4, c = (f & 15) * 4;
        *(float4*)&Qs[r * 64 + c] = *(const float4*)&Qg[(size_t)r * HDIM + c];
    }

    float O[4][4];
    float m_i[4], l_i[4];
    #pragma unroll
    for (int i = 0; i < 4; i++) {
        m_i[i] = -1e30f; l_i[i] = 0.f;
        #pragma unroll
        for (int j = 0; j < 4; j++) O[i][j] = 0.f;
    }

    for (int kt = 0; kt < SEQ; kt += 64) {
        __syncthreads();   // Q ready (iter 0) / previous PV done reading Vs,Ps
        #pragma unroll
        for (int it = 0; it < 4; it++) {
            int f = tid + it * 256;
            int r = f >> 4, c = (f & 15) * 4;
            *(float4*)&Ks[r * KS_STRIDE + c] = *(const float4*)&Kg[(size_t)(kt + r) * HDIM + c];
            *(float4*)&Vs[r * 64 + c]        = *(const float4*)&Vg[(size_t)(kt + r) * HDIM + c];
        }
        __syncthreads();

        // S = Q @ K^T (Q pre-scaled)
        float S[4][4];
        #pragma unroll
        for (int i = 0; i < 4; i++)
            #pragma unroll
            for (int j = 0; j < 4; j++) S[i][j] = 0.f;

        #pragma unroll
        for (int k4 = 0; k4 < 16; k4++) {
            float a[4][4], b[4][4];
            #pragma unroll
            for (int i = 0; i < 4; i++)
                *(float4*)a[i] = *(float4*)&Qs[(ty * 4 + i) * 64 + k4 * 4];
            #pragma unroll
            for (int j = 0; j < 4; j++)
                *(float4*)b[j] = *(float4*)&Ks[(tx + 16 * j) * KS_STRIDE + k4 * 4];
            #pragma unroll
            for (int i = 0; i < 4; i++)
                #pragma unroll
                for (int j = 0; j < 4; j++)
                    #pragma unroll
                    for (int c = 0; c < 4; c++)
                        S[i][j] = fmaf(a[i][c], b[j][c], S[i][j]);
        }

        // online softmax (row-group = 16 threads with equal ty)
        float P[4][4];
        #pragma unroll
        for (int i = 0; i < 4; i++) {
            float r = fmaxf(fmaxf(S[i][0], S[i][1]), fmaxf(S[i][2], S[i][3]));
            #pragma unroll
            for (int off = 8; off; off >>= 1)
                r = fmaxf(r, __shfl_xor_sync(0xffffffffu, r, off, 16));
            float mn = fmaxf(m_i[i], r);
            float corr = __expf(m_i[i] - mn);
            m_i[i] = mn;
            l_i[i] *= corr;
            #pragma unroll
            for (int j = 0; j < 4; j++) O[i][j] *= corr;
            float s = 0.f;
            #pragma unroll
            for (int j = 0; j < 4; j++) { P[i][j] = __expf(S[i][j] - mn); s += P[i][j]; }
            #pragma unroll
            for (int off = 8; off; off >>= 1)
                s += __shfl_xor_sync(0xffffffffu, s, off, 16);
            l_i[i] += s;
        }

        #pragma unroll
        for (int i = 0; i < 4; i++)
            #pragma unroll
            for (int j = 0; j < 4; j++)
                Ps[(ty * 4 + i) * 64 + tx + 16 * j] = P[i][j];
        __syncthreads();

        // O += P @ V
        #pragma unroll
        for (int k4 = 0; k4 < 16; k4++) {
            float p[4][4];
            #pragma unroll
            for (int i = 0; i < 4; i++)
                *(float4*)p[i] = *(float4*)&Ps[(ty * 4 + i) * 64 + k4 * 4];
            #pragma unroll
            for (int kk = 0; kk < 4; kk++) {
                float v[4];
                #pragma unroll
                for (int j = 0; j < 4; j++)
                    v[j] = Vs[(k4 * 4 + kk) * 64 + tx + 16 * j];
                #pragma unroll
                for (int i = 0; i < 4; i++)
                    #pragma unroll
                    for (int j = 0; j < 4; j++)
                        O[i][j] = fmaf(p[i][kk], v[j], O[i][j]);
            }
        }
    }

    // finalize + write to [B,N,H*D]
    const int bb = bh >> 3, h = bh & 7;
    #pragma unroll
    for (int i = 0; i < 4; i++) {
        float inv = 1.0f / l_i[i];
        int n = q0 + ty * 4 + i;
        float* dst = g_ao + ((size_t)(bb * SEQ + n)) * INNER + h * HDIM;
        #pragma unroll
        for (int j = 0; j < 4; j++)
            dst[tx + 16 * j] = O[i][j] * inv;
    }
}

// ---------------------------------------------------------------------------
// Kernel 3: output projection  out = AO @ Wproj + b
// ---------------------------------------------------------------------------
__global__ __launch_bounds__(256, 2) void proj_gemm_kernel(
    const float* __restrict__ W,     // [512, 1024]
    const float* __restrict__ bias,  // [1024]
    float* __restrict__ out)         // [8192, 1024]
{
    __shared__ float As[16][128];
    __shared__ float Bs[16][128];
    const int tid  = threadIdx.x;
    const int tx   = tid & 15, ty = tid >> 4;
    const int row0 = blockIdx.y * 128;
    const int col0 = blockIdx.x * 128;

    float acc[8][8];
    #pragma unroll
    for (int i = 0; i < 8; i++)
        #pragma unroll
        for (int j = 0; j < 8; j++) acc[i][j] = 0.f;

    for (int kt = 0; kt < INNER; kt += 16) {
        #pragma unroll
        for (int it = 0; it < 2; it++) {
            int f = tid + it * 256;
            int r = f >> 2, c4 = (f & 3) * 4;
            float4 v = *(const float4*)&g_ao[(size_t)(row0 + r) * INNER + kt + c4];
            As[c4 + 0][r] = v.x; As[c4 + 1][r] = v.y;
            As[c4 + 2][r] = v.z; As[c4 + 3][r] = v.w;
        }
        #pragma unroll
        for (int it = 0; it < 2; it++) {
            int f = tid + it * 256;
            int r = f >> 5, c4 = (f & 31) * 4;
            *(float4*)&Bs[r][c4] = *(const float4*)&W[(size_t)(kt + r) * EMBED + col0 + c4];
        }
        __syncthreads();
        #pragma unroll
        for (int k = 0; k < 16; k++) {
            float a[8], b[8];
            *(float4*)&a[0] = *(float4*)&As[k][ty * 8];
            *(float4*)&a[4] = *(float4*)&As[k][ty * 8 + 4];
            *(float4*)&b[0] = *(float4*)&Bs[k][tx * 8];
            *(float4*)&b[4] = *(float4*)&Bs[k][tx * 8 + 4];
            #pragma unroll
            for (int i = 0; i < 8; i++)
                #pragma unroll
                for (int j = 0; j < 8; j++)
                    acc[i][j] = fmaf(a[i], b[j], acc[i][j]);
        }
        __syncthreads();
    }

    #pragma unroll
    for (int i = 0; i < 8; i++) {
        int m = row0 + ty * 8 + i;
        #pragma unroll
        for (int jj = 0; jj < 2; jj++) {
            int o = col0 + tx * 8 + jj * 4;
            float4 o4;
            o4.x = acc[i][jj * 4 + 0] + bias[o + 0];
            o4.y = acc[i][jj * 4 + 1] + bias[o + 1];
            o4.z = acc[i][jj * 4 + 2] + bias[o + 2];
            o4.w = acc[i][jj * 4 + 3] + bias[o + 3];
            *(float4*)&out[(size_t)m * EMBED + o] = o4;
        }
    }
}

// ---------------------------------------------------------------------------
extern "C" void kernel_launch(void* const* d_in, const int* in_sizes, int n_in,
                              void* d_out, int out_size)
{
    const float* X     = (const float*)d_in[0];   // representation [2,4096,1024]
    const float* Wqkv  = (const float*)d_in[1];   // [1024, 1536]
    const float* Bqkv  = (const float*)d_in[2];   // [1536]
    const float* Wproj = (const float*)d_in[3];   // [512, 1024]
    const float* Bproj = (const float*)d_in[4];   // [1024]
    float* out = (float*)d_out;                   // [2,4096,1024]

    cudaFuncSetAttribute(attn_kernel,
                         cudaFuncAttributeMaxDynamicSharedMemorySize,
                         ATTN_SMEM_BYTES);

    qkv_gemm_kernel<<<dim3(QKVN / 128, MROWS / 128), 256>>>(X, Wqkv, Bqkv);
    attn_kernel<<<dim3(SEQ / 64, BATCH * NHEAD), 256, ATTN_SMEM_BYTES>>>();
    proj_gemm_kernel<<<dim3(EMBED / 128, MROWS / 128), 256>>>(Wproj, Bproj, out);
}

// round 4
// speedup vs baseline: 2.9250x; 2.9250x over previous
#include <cuda_runtime.h>
#include <math.h>

#define EMBED 1024
#define QKVN  1536
#define INNER 512
#define NHEAD 8
#define HDIM  64
#define BATCH 2
#define SEQ   4096
#define MROWS (BATCH * SEQ)   // 8192

// Scratch (allocation-free rule: __device__ globals)
__device__ float g_q[BATCH * NHEAD * SEQ * HDIM];   // [B,H,N,D], pre-scaled by 0.125
__device__ float g_k[BATCH * NHEAD * SEQ * HDIM];
__device__ float g_v[BATCH * NHEAD * SEQ * HDIM];
__device__ float g_ao[MROWS * INNER];               // attention out, [B,N,H*D]

// ---------------------------------------------------------------------------
// TF32 mma helpers
// ---------------------------------------------------------------------------
__device__ __forceinline__ unsigned f2tf(float f) {
    unsigned u;
    asm("cvt.rna.tf32.f32 %0, %1;" : "=r"(u) : "f"(f));
    return u;
}

__device__ __forceinline__ void mma8(float* c, const unsigned* a, const unsigned* b) {
    asm volatile(
        "mma.sync.aligned.m16n8k8.row.col.f32.tf32.tf32.f32 "
        "{%0,%1,%2,%3}, {%4,%5,%6,%7}, {%8,%9}, {%0,%1,%2,%3};"
        : "+f"(c[0]), "+f"(c[1]), "+f"(c[2]), "+f"(c[3])
        : "r"(a[0]), "r"(a[1]), "r"(a[2]), "r"(a[3]), "r"(b[0]), "r"(b[1]));
}

// ---------------------------------------------------------------------------
// Shared GEMM mainloop: C[128x128] tile, BK=32, 256 threads (8 warps 2x4),
// warp tile 64x32 (4 m16 x 4 n8). tf32-rounded at smem store.
// As: [128][AST] m-major (AST=36, ≡4 mod 32 -> a-frag conflict-free)
// Bs: [32][BST]  k-major (BST=136, ≡8 mod 32 -> b-frag conflict-free)
// ---------------------------------------------------------------------------
#define AST 36
#define BST 136

template<int KDIM>
__device__ __forceinline__ void gemm_mainloop(
    const float* __restrict__ A, int lda,
    const float* __restrict__ B, int ldb,
    float acc[4][4][4], float* As, float* Bs, int row0, int col0)
{
    const int tid  = threadIdx.x;
    const int lane = tid & 31;
    const int warp = tid >> 5;
    const int wm   = (warp >> 2) * 64;
    const int wn   = (warp & 3) * 32;
    const int g    = lane >> 2, t = lane & 3;

    for (int kt = 0; kt < KDIM; kt += 32) {
        #pragma unroll
        for (int i = 0; i < 4; i++) {           // A tile 128x32
            int f = tid + i * 256;
            int r = f >> 3, c = (f & 7) * 4;
            float4 v = *(const float4*)&A[(size_t)(row0 + r) * lda + kt + c];
            unsigned* dst = (unsigned*)&As[r * AST + c];
            dst[0] = f2tf(v.x); dst[1] = f2tf(v.y);
            dst[2] = f2tf(v.z); dst[3] = f2tf(v.w);
        }
        #pragma unroll
        for (int i = 0; i < 4; i++) {           // B tile 32x128
            int f = tid + i * 256;
            int r = f >> 5, c = (f & 31) * 4;
            float4 v = *(const float4*)&B[(size_t)(kt + r) * ldb + col0 + c];
            unsigned* dst = (unsigned*)&Bs[r * BST + c];
            dst[0] = f2tf(v.x); dst[1] = f2tf(v.y);
            dst[2] = f2tf(v.z); dst[3] = f2tf(v.w);
        }
        __syncthreads();

        const unsigned* Au = (const unsigned*)As;
        const unsigned* Bu = (const unsigned*)Bs;
        #pragma unroll
        for (int ks = 0; ks < 4; ks++) {
            unsigned a[4][4], b[4][2];
            #pragma unroll
            for (int mt = 0; mt < 4; mt++) {
                int m = wm + mt * 16;
                a[mt][0] = Au[(m + g) * AST + ks * 8 + t];
                a[mt][1] = Au[(m + g + 8) * AST + ks * 8 + t];
                a[mt][2] = Au[(m + g) * AST + ks * 8 + t + 4];
                a[mt][3] = Au[(m + g + 8) * AST + ks * 8 + t + 4];
            }
            #pragma unroll
            for (int nt = 0; nt < 4; nt++) {
                int n = wn + nt * 8 + g;
                b[nt][0] = Bu[(ks * 8 + t) * BST + n];
                b[nt][1] = Bu[(ks * 8 + t + 4) * BST + n];
            }
            #pragma unroll
            for (int mt = 0; mt < 4; mt++)
                #pragma unroll
                for (int nt = 0; nt < 4; nt++)
                    mma8(acc[mt][nt], a[mt], b[nt]);
        }
        __syncthreads();
    }
}

// ---------------------------------------------------------------------------
// Kernel 1: QKV projection, scatter to Q/K/V [B,H,N,D]; Q pre-scaled.
// ---------------------------------------------------------------------------
__global__ __launch_bounds__(256) void qkv_gemm_kernel(
    const float* __restrict__ A,     // [8192, 1024]
    const float* __restrict__ W,     // [1024, 1536]
    const float* __restrict__ bias)  // [1536]
{
    __shared__ float As[128 * AST];
    __shared__ float Bs[32 * BST];
    const int tid  = threadIdx.x;
    const int lane = tid & 31, warp = tid >> 5;
    const int wm = (warp >> 2) * 64, wn = (warp & 3) * 32;
    const int g = lane >> 2, t = lane & 3;
    const int row0 = blockIdx.y * 128;
    const int col0 = blockIdx.x * 128;

    float acc[4][4][4];
    #pragma unroll
    for (int mt = 0; mt < 4; mt++)
        #pragma unroll
        for (int nt = 0; nt < 4; nt++)
            #pragma unroll
            for (int r = 0; r < 4; r++) acc[mt][nt][r] = 0.f;

    gemm_mainloop<EMBED>(A, EMBED, W, QKVN, acc, As, Bs, row0, col0);

    #pragma unroll
    for (int mt = 0; mt < 4; mt++) {
        #pragma unroll
        for (int half = 0; half < 2; half++) {
            int m  = row0 + wm + mt * 16 + g + half * 8;
            int bb = m >> 12;
            int n  = m & (SEQ - 1);
            #pragma unroll
            for (int nt = 0; nt < 4; nt++) {
                #pragma unroll
                for (int jj = 0; jj < 2; jj++) {
                    int o = col0 + wn + nt * 8 + t * 2 + jj;
                    float val = acc[mt][nt][half * 2 + jj] + bias[o];
                    int part  = o >> 9;
                    int inner = o & 511;
                    int h = inner >> 6, d = inner & 63;
                    size_t idx = (((size_t)(bb * NHEAD + h)) * SEQ + n) * HDIM + d;
                    if (part == 0)      g_q[idx] = val * 0.125f;
                    else if (part == 1) g_k[idx] = val;
                    else                g_v[idx] = val;
                }
            }
        }
    }
}

// ---------------------------------------------------------------------------
// Kernel 2: flash attention with tf32 mma. BQ=64, BKV=64, 128 threads.
// Warp w owns q rows [w*16, w*16+16). Fragments:
//   S = Q K^T : A from Qs (stride 68 ≡4), B from Ks (stride 68 ≡4 works: 4g+t)
//   O += P V  : A from Ps (stride 68),    B from Vs (stride 72 ≡8: 8t+g)
// ---------------------------------------------------------------------------
#define QST 68
#define KST 68
#define VST 72
#define PST 68
#define ATT_SMEM_BYTES ((64 * QST + 64 * KST + 64 * VST + 64 * PST) * 4)  // 70656

__global__ __launch_bounds__(128) void attn_kernel()
{
    extern __shared__ float sm[];
    float* Qs = sm;
    float* Ks = Qs + 64 * QST;
    float* Vs = Ks + 64 * KST;
    float* Ps = Vs + 64 * VST;

    const int tid  = threadIdx.x;
    const int lane = tid & 31, warp = tid >> 5;
    const int g = lane >> 2, t = lane & 3;
    const int bh = blockIdx.y;
    const int q0 = blockIdx.x * 64;
    const int w16 = warp * 16;

    const float* Qg = g_q + ((size_t)bh * SEQ + q0) * HDIM;
    const float* Kg = g_k + (size_t)bh * SEQ * HDIM;
    const float* Vg = g_v + (size_t)bh * SEQ * HDIM;

    // Load + round Q (64x64)
    #pragma unroll
    for (int i = 0; i < 8; i++) {
        int f = tid + i * 128;
        int r = f >> 4, c = (f & 15) * 4;
        float4 v = *(const float4*)&Qg[(size_t)r * HDIM + c];
        unsigned* dst = (unsigned*)&Qs[r * QST + c];
        dst[0] = f2tf(v.x); dst[1] = f2tf(v.y);
        dst[2] = f2tf(v.z); dst[3] = f2tf(v.w);
    }

    float o[8][4];
    float m_i[2], l_i[2];
    #pragma unroll
    for (int nt = 0; nt < 8; nt++)
        #pragma unroll
        for (int r = 0; r < 4; r++) o[nt][r] = 0.f;
    m_i[0] = m_i[1] = -1e30f;
    l_i[0] = l_i[1] = 0.f;

    const unsigned* Qu = (const unsigned*)Qs;
    const unsigned* Ku = (const unsigned*)Ks;
    const unsigned* Vu = (const unsigned*)Vs;
    const unsigned* Pu = (const unsigned*)Ps;

    for (int kt = 0; kt < SEQ; kt += 64) {
        __syncthreads();   // prior tile fully consumed (also orders Q on iter 0)
        #pragma unroll
        for (int i = 0; i < 8; i++) {
            int f = tid + i * 128;
            int r = f >> 4, c = (f & 15) * 4;
            float4 kv = *(const float4*)&Kg[(size_t)(kt + r) * HDIM + c];
            unsigned* kd = (unsigned*)&Ks[r * KST + c];
            kd[0] = f2tf(kv.x); kd[1] = f2tf(kv.y);
            kd[2] = f2tf(kv.z); kd[3] = f2tf(kv.w);
            float4 vv = *(const float4*)&Vg[(size_t)(kt + r) * HDIM + c];
            unsigned* vd = (unsigned*)&Vs[r * VST + c];
            vd[0] = f2tf(vv.x); vd[1] = f2tf(vv.y);
            vd[2] = f2tf(vv.z); vd[3] = f2tf(vv.w);
        }
        __syncthreads();

        // ---- S = Q K^T : 16 x 64 per warp ----
        float s[8][4];
        #pragma unroll
        for (int nt = 0; nt < 8; nt++)
            #pragma unroll
            for (int r = 0; r < 4; r++) s[nt][r] = 0.f;

        #pragma unroll
        for (int ks = 0; ks < 8; ks++) {
            unsigned a[4];
            a[0] = Qu[(w16 + g) * QST + ks * 8 + t];
            a[1] = Qu[(w16 + g + 8) * QST + ks * 8 + t];
            a[2] = Qu[(w16 + g) * QST + ks * 8 + t + 4];
            a[3] = Qu[(w16 + g + 8) * QST + ks * 8 + t + 4];
            #pragma unroll
            for (int nt = 0; nt < 8; nt++) {
                unsigned b[2];
                b[0] = Ku[(nt * 8 + g) * KST + ks * 8 + t];
                b[1] = Ku[(nt * 8 + g) * KST + ks * 8 + t + 4];
                mma8(s[nt], a, b);
            }
        }

        // ---- online softmax on C-fragment layout ----
        __syncwarp();      // prior PV reads of Ps done before overwrite
        #pragma unroll
        for (int half = 0; half < 2; half++) {
            float mx = -1e30f;
            #pragma unroll
            for (int nt = 0; nt < 8; nt++)
                mx = fmaxf(mx, fmaxf(s[nt][half * 2], s[nt][half * 2 + 1]));
            mx = fmaxf(mx, __shfl_xor_sync(0xffffffffu, mx, 1));
            mx = fmaxf(mx, __shfl_xor_sync(0xffffffffu, mx, 2));
            float mn   = fmaxf(m_i[half], mx);
            float corr = __expf(m_i[half] - mn);
            m_i[half] = mn;
            float sum = 0.f;
            #pragma unroll
            for (int nt = 0; nt < 8; nt++) {
                float p0 = __expf(s[nt][half * 2]     - mn);
                float p1 = __expf(s[nt][half * 2 + 1] - mn);
                sum += p0 + p1;
                unsigned* pd = (unsigned*)&Ps[(w16 + g + half * 8) * PST + nt * 8 + t * 2];
                pd[0] = f2tf(p0); pd[1] = f2tf(p1);
                o[nt][half * 2]     *= corr;
                o[nt][half * 2 + 1] *= corr;
            }
            sum += __shfl_xor_sync(0xffffffffu, sum, 1);
            sum += __shfl_xor_sync(0xffffffffu, sum, 2);
            l_i[half] = l_i[half] * corr + sum;
        }
        __syncwarp();      // P visible to whole warp before PV loads

        // ---- O += P V ----
        #pragma unroll
        for (int ks = 0; ks < 8; ks++) {
            unsigned a[4];
            a[0] = Pu[(w16 + g) * PST + ks * 8 + t];
            a[1] = Pu[(w16 + g + 8) * PST + ks * 8 + t];
            a[2] = Pu[(w16 + g) * PST + ks * 8 + t + 4];
            a[3] = Pu[(w16 + g + 8) * PST + ks * 8 + t + 4];
            #pragma unroll
            for (int nt = 0; nt < 8; nt++) {
                unsigned b[2];
                b[0] = Vu[(ks * 8 + t) * VST + nt * 8 + g];
                b[1] = Vu[(ks * 8 + t + 4) * VST + nt * 8 + g];
                mma8(o[nt], a, b);
            }
        }
    }

    // finalize + write [B,N,H*D]
    const int bb = bh >> 3, h = bh & 7;
    #pragma unroll
    for (int half = 0; half < 2; half++) {
        float inv = 1.0f / l_i[half];
        int n = q0 + w16 + g + half * 8;
        float* dst = g_ao + ((size_t)(bb * SEQ + n)) * INNER + h * HDIM;
        #pragma unroll
        for (int nt = 0; nt < 8; nt++) {
            float2 v2;
            v2.x = o[nt][half * 2]     * inv;
            v2.y = o[nt][half * 2 + 1] * inv;
            *(float2*)&dst[nt * 8 + t * 2] = v2;
        }
    }
}

// ---------------------------------------------------------------------------
// Kernel 3: output projection  out = AO @ Wproj + b
// ---------------------------------------------------------------------------
__global__ __launch_bounds__(256) void proj_gemm_kernel(
    const float* __restrict__ W,     // [512, 1024]
    const float* __restrict__ bias,  // [1024]
    float* __restrict__ out)         // [8192, 1024]
{
    __shared__ float As[128 * AST];
    __shared__ float Bs[32 * BST];
    const int tid  = threadIdx.x;
    const int lane = tid & 31, warp = tid >> 5;
    const int wm = (warp >> 2) * 64, wn = (warp & 3) * 32;
    const int g = lane >> 2, t = lane & 3;
    const int row0 = blockIdx.y * 128;
    const int col0 = blockIdx.x * 128;

    float acc[4][4][4];
    #pragma unroll
    for (int mt = 0; mt < 4; mt++)
        #pragma unroll
        for (int nt = 0; nt < 4; nt++)
            #pragma unroll
            for (int r = 0; r < 4; r++) acc[mt][nt][r] = 0.f;

    gemm_mainloop<INNER>(g_ao, INNER, W, EMBED, acc, As, Bs, row0, col0);

    #pragma unroll
    for (int mt = 0; mt < 4; mt++) {
        #pragma unroll
        for (int half = 0; half < 2; half++) {
            int m = row0 + wm + mt * 16 + g + half * 8;
            #pragma unroll
            for (int nt = 0; nt < 4; nt++) {
                int n = col0 + wn + nt * 8 + t * 2;
                float2 v2;
                v2.x = acc[mt][nt][half * 2]     + bias[n];
                v2.y = acc[mt][nt][half * 2 + 1] + bias[n + 1];
                *(float2*)&out[(size_t)m * EMBED + n] = v2;
            }
        }
    }
}

// ---------------------------------------------------------------------------
extern "C" void kernel_launch(void* const* d_in, const int* in_sizes, int n_in,
                              void* d_out, int out_size)
{
    const float* X     = (const float*)d_in[0];
    const float* Wqkv  = (const float*)d_in[1];
    const float* Bqkv  = (const float*)d_in[2];
    const float* Wproj = (const float*)d_in[3];
    const float* Bproj = (const float*)d_in[4];
    float* out = (float*)d_out;

    cudaFuncSetAttribute(attn_kernel,
                         cudaFuncAttributeMaxDynamicSharedMemorySize,
                         ATT_SMEM_BYTES);

    qkv_gemm_kernel<<<dim3(QKVN / 128, MROWS / 128), 256>>>(X, Wqkv, Bqkv);
    attn_kernel<<<dim3(SEQ / 64, BATCH * NHEAD), 128, ATT_SMEM_BYTES>>>();
    proj_gemm_kernel<<<dim3(EMBED / 128, MROWS / 128), 256>>>(Wproj, Bproj, out);
}

// round 5
// speedup vs baseline: 2.9252x; 1.0001x over previous
#include <cuda_runtime.h>
#include <math.h>

#define EMBED 1024
#define QKVN  1536
#define INNER 512
#define NHEAD 8
#define HDIM  64
#define BATCH 2
#define SEQ   4096
#define MROWS (BATCH * SEQ)   // 8192

// Scratch (allocation-free rule: __device__ globals)
__device__ float g_q[BATCH * NHEAD * SEQ * HDIM];   // [B,H,N,D], pre-scaled by 0.125
__device__ float g_k[BATCH * NHEAD * SEQ * HDIM];
__device__ float g_v[BATCH * NHEAD * SEQ * HDIM];
__device__ float g_ao[MROWS * INNER];               // attention out, [B,N,H*D]

// ---------------------------------------------------------------------------
// TF32 mma helpers
// ---------------------------------------------------------------------------
__device__ __forceinline__ unsigned f2tf(float f) {
    unsigned u;
    asm("cvt.rna.tf32.f32 %0, %1;" : "=r"(u) : "f"(f));
    return u;
}

__device__ __forceinline__ void mma8(float* c, const unsigned* a, const unsigned* b) {
    asm volatile(
        "mma.sync.aligned.m16n8k8.row.col.f32.tf32.tf32.f32 "
        "{%0,%1,%2,%3}, {%4,%5,%6,%7}, {%8,%9}, {%0,%1,%2,%3};"
        : "+f"(c[0]), "+f"(c[1]), "+f"(c[2]), "+f"(c[3])
        : "r"(a[0]), "r"(a[1]), "r"(a[2]), "r"(a[3]), "r"(b[0]), "r"(b[1]));
}

// ---------------------------------------------------------------------------
// Shared GEMM mainloop: C[128x128] tile, BK=32, 256 threads (8 warps 2x4),
// warp tile 64x32 (4 m16 x 4 n8). tf32-rounded at smem store.
// As: [128][AST] m-major (AST=36, ≡4 mod 32 -> a-frag conflict-free)
// Bs: [32][BST]  k-major (BST=136, ≡8 mod 32 -> b-frag conflict-free)
// ---------------------------------------------------------------------------
#define AST 36
#define BST 136

template<int KDIM>
__device__ __forceinline__ void gemm_mainloop(
    const float* __restrict__ A, int lda,
    const float* __restrict__ B, int ldb,
    float acc[4][4][4], float* As, float* Bs, int row0, int col0)
{
    const int tid  = threadIdx.x;
    const int lane = tid & 31;
    const int warp = tid >> 5;
    const int wm   = (warp >> 2) * 64;
    const int wn   = (warp & 3) * 32;
    const int g    = lane >> 2, t = lane & 3;

    for (int kt = 0; kt < KDIM; kt += 32) {
        #pragma unroll
        for (int i = 0; i < 4; i++) {           // A tile 128x32
            int f = tid + i * 256;
            int r = f >> 3, c = (f & 7) * 4;
            float4 v = *(const float4*)&A[(size_t)(row0 + r) * lda + kt + c];
            unsigned* dst = (unsigned*)&As[r * AST + c];
            dst[0] = f2tf(v.x); dst[1] = f2tf(v.y);
            dst[2] = f2tf(v.z); dst[3] = f2tf(v.w);
        }
        #pragma unroll
        for (int i = 0; i < 4; i++) {           // B tile 32x128
            int f = tid + i * 256;
            int r = f >> 5, c = (f & 31) * 4;
            float4 v = *(const float4*)&B[(size_t)(kt + r) * ldb + col0 + c];
            unsigned* dst = (unsigned*)&Bs[r * BST + c];
            dst[0] = f2tf(v.x); dst[1] = f2tf(v.y);
            dst[2] = f2tf(v.z); dst[3] = f2tf(v.w);
        }
        __syncthreads();

        const unsigned* Au = (const unsigned*)As;
        const unsigned* Bu = (const unsigned*)Bs;
        #pragma unroll
        for (int ks = 0; ks < 4; ks++) {
            unsigned a[4][4], b[4][2];
            #pragma unroll
            for (int mt = 0; mt < 4; mt++) {
                int m = wm + mt * 16;
                a[mt][0] = Au[(m + g) * AST + ks * 8 + t];
                a[mt][1] = Au[(m + g + 8) * AST + ks * 8 + t];
                a[mt][2] = Au[(m + g) * AST + ks * 8 + t + 4];
                a[mt][3] = Au[(m + g + 8) * AST + ks * 8 + t + 4];
            }
            #pragma unroll
            for (int nt = 0; nt < 4; nt++) {
                int n = wn + nt * 8 + g;
                b[nt][0] = Bu[(ks * 8 + t) * BST + n];
                b[nt][1] = Bu[(ks * 8 + t + 4) * BST + n];
            }
            #pragma unroll
            for (int mt = 0; mt < 4; mt++)
                #pragma unroll
                for (int nt = 0; nt < 4; nt++)
                    mma8(acc[mt][nt], a[mt], b[nt]);
        }
        __syncthreads();
    }
}

// ---------------------------------------------------------------------------
// Kernel 1: QKV projection, scatter to Q/K/V [B,H,N,D]; Q pre-scaled.
// ---------------------------------------------------------------------------
__global__ __launch_bounds__(256) void qkv_gemm_kernel(
    const float* __restrict__ A,     // [8192, 1024]
    const float* __restrict__ W,     // [1024, 1536]
    const float* __restrict__ bias)  // [1536]
{
    __shared__ float As[128 * AST];
    __shared__ float Bs[32 * BST];
    const int tid  = threadIdx.x;
    const int lane = tid & 31, warp = tid >> 5;
    const int wm = (warp >> 2) * 64, wn = (warp & 3) * 32;
    const int g = lane >> 2, t = lane & 3;
    const int row0 = blockIdx.y * 128;
    const int col0 = blockIdx.x * 128;

    float acc[4][4][4];
    #pragma unroll
    for (int mt = 0; mt < 4; mt++)
        #pragma unroll
        for (int nt = 0; nt < 4; nt++)
            #pragma unroll
            for (int r = 0; r < 4; r++) acc[mt][nt][r] = 0.f;

    gemm_mainloop<EMBED>(A, EMBED, W, QKVN, acc, As, Bs, row0, col0);

    #pragma unroll
    for (int mt = 0; mt < 4; mt++) {
        #pragma unroll
        for (int half = 0; half < 2; half++) {
            int m  = row0 + wm + mt * 16 + g + half * 8;
            int bb = m >> 12;
            int n  = m & (SEQ - 1);
            #pragma unroll
            for (int nt = 0; nt < 4; nt++) {
                #pragma unroll
                for (int jj = 0; jj < 2; jj++) {
                    int o = col0 + wn + nt * 8 + t * 2 + jj;
                    float val = acc[mt][nt][half * 2 + jj] + bias[o];
                    int part  = o >> 9;
                    int inner = o & 511;
                    int h = inner >> 6, d = inner & 63;
                    size_t idx = (((size_t)(bb * NHEAD + h)) * SEQ + n) * HDIM + d;
                    if (part == 0)      g_q[idx] = val * 0.125f;
                    else if (part == 1) g_k[idx] = val;
                    else                g_v[idx] = val;
                }
            }
        }
    }
}

// ---------------------------------------------------------------------------
// Kernel 2: flash attention with tf32 mma. BQ=64, BKV=64, 128 threads.
// Warp w owns q rows [w*16, w*16+16). Fragments:
//   S = Q K^T : A from Qs (stride 68 ≡4), B from Ks (stride 68 ≡4 works: 4g+t)
//   O += P V  : A from Ps (stride 68),    B from Vs (stride 72 ≡8: 8t+g)
// ---------------------------------------------------------------------------
#define QST 68
#define KST 68
#define VST 72
#define PST 68
#define ATT_SMEM_BYTES ((64 * QST + 64 * KST + 64 * VST + 64 * PST) * 4)  // 70656

__global__ __launch_bounds__(128) void attn_kernel()
{
    extern __shared__ float sm[];
    float* Qs = sm;
    float* Ks = Qs + 64 * QST;
    float* Vs = Ks + 64 * KST;
    float* Ps = Vs + 64 * VST;

    const int tid  = threadIdx.x;
    const int lane = tid & 31, warp = tid >> 5;
    const int g = lane >> 2, t = lane & 3;
    const int bh = blockIdx.y;
    const int q0 = blockIdx.x * 64;
    const int w16 = warp * 16;

    const float* Qg = g_q + ((size_t)bh * SEQ + q0) * HDIM;
    const float* Kg = g_k + (size_t)bh * SEQ * HDIM;
    const float* Vg = g_v + (size_t)bh * SEQ * HDIM;

    // Load + round Q (64x64)
    #pragma unroll
    for (int i = 0; i < 8; i++) {
        int f = tid + i * 128;
        int r = f >> 4, c = (f & 15) * 4;
        float4 v = *(const float4*)&Qg[(size_t)r * HDIM + c];
        unsigned* dst = (unsigned*)&Qs[r * QST + c];
        dst[0] = f2tf(v.x); dst[1] = f2tf(v.y);
        dst[2] = f2tf(v.z); dst[3] = f2tf(v.w);
    }

    float o[8][4];
    float m_i[2], l_i[2];
    #pragma unroll
    for (int nt = 0; nt < 8; nt++)
        #pragma unroll
        for (int r = 0; r < 4; r++) o[nt][r] = 0.f;
    m_i[0] = m_i[1] = -1e30f;
    l_i[0] = l_i[1] = 0.f;

    const unsigned* Qu = (const unsigned*)Qs;
    const unsigned* Ku = (const unsigned*)Ks;
    const unsigned* Vu = (const unsigned*)Vs;
    const unsigned* Pu = (const unsigned*)Ps;

    for (int kt = 0; kt < SEQ; kt += 64) {
        __syncthreads();   // prior tile fully consumed (also orders Q on iter 0)
        #pragma unroll
        for (int i = 0; i < 8; i++) {
            int f = tid + i * 128;
            int r = f >> 4, c = (f & 15) * 4;
            float4 kv = *(const float4*)&Kg[(size_t)(kt + r) * HDIM + c];
            unsigned* kd = (unsigned*)&Ks[r * KST + c];
            kd[0] = f2tf(kv.x); kd[1] = f2tf(kv.y);
            kd[2] = f2tf(kv.z); kd[3] = f2tf(kv.w);
            float4 vv = *(const float4*)&Vg[(size_t)(kt + r) * HDIM + c];
            unsigned* vd = (unsigned*)&Vs[r * VST + c];
            vd[0] = f2tf(vv.x); vd[1] = f2tf(vv.y);
            vd[2] = f2tf(vv.z); vd[3] = f2tf(vv.w);
        }
        __syncthreads();

        // ---- S = Q K^T : 16 x 64 per warp ----
        float s[8][4];
        #pragma unroll
        for (int nt = 0; nt < 8; nt++)
            #pragma unroll
            for (int r = 0; r < 4; r++) s[nt][r] = 0.f;

        #pragma unroll
        for (int ks = 0; ks < 8; ks++) {
            unsigned a[4];
            a[0] = Qu[(w16 + g) * QST + ks * 8 + t];
            a[1] = Qu[(w16 + g + 8) * QST + ks * 8 + t];
            a[2] = Qu[(w16 + g) * QST + ks * 8 + t + 4];
            a[3] = Qu[(w16 + g + 8) * QST + ks * 8 + t + 4];
            #pragma unroll
            for (int nt = 0; nt < 8; nt++) {
                unsigned b[2];
                b[0] = Ku[(nt * 8 + g) * KST + ks * 8 + t];
                b[1] = Ku[(nt * 8 + g) * KST + ks * 8 + t + 4];
                mma8(s[nt], a, b);
            }
        }

        // ---- online softmax on C-fragment layout ----
        __syncwarp();      // prior PV reads of Ps done before overwrite
        #pragma unroll
        for (int half = 0; half < 2; half++) {
            float mx = -1e30f;
            #pragma unroll
            for (int nt = 0; nt < 8; nt++)
                mx = fmaxf(mx, fmaxf(s[nt][half * 2], s[nt][half * 2 + 1]));
            mx = fmaxf(mx, __shfl_xor_sync(0xffffffffu, mx, 1));
            mx = fmaxf(mx, __shfl_xor_sync(0xffffffffu, mx, 2));
            float mn   = fmaxf(m_i[half], mx);
            float corr = __expf(m_i[half] - mn);
            m_i[half] = mn;
            float sum = 0.f;
            #pragma unroll
            for (int nt = 0; nt < 8; nt++) {
                float p0 = __expf(s[nt][half * 2]     - mn);
                float p1 = __expf(s[nt][half * 2 + 1] - mn);
                sum += p0 + p1;
                unsigned* pd = (unsigned*)&Ps[(w16 + g + half * 8) * PST + nt * 8 + t * 2];
                pd[0] = f2tf(p0); pd[1] = f2tf(p1);
                o[nt][half * 2]     *= corr;
                o[nt][half * 2 + 1] *= corr;
            }
            sum += __shfl_xor_sync(0xffffffffu, sum, 1);
            sum += __shfl_xor_sync(0xffffffffu, sum, 2);
            l_i[half] = l_i[half] * corr + sum;
        }
        __syncwarp();      // P visible to whole warp before PV loads

        // ---- O += P V ----
        #pragma unroll
        for (int ks = 0; ks < 8; ks++) {
            unsigned a[4];
            a[0] = Pu[(w16 + g) * PST + ks * 8 + t];
            a[1] = Pu[(w16 + g + 8) * PST + ks * 8 + t];
            a[2] = Pu[(w16 + g) * PST + ks * 8 + t + 4];
            a[3] = Pu[(w16 + g + 8) * PST + ks * 8 + t + 4];
            #pragma unroll
            for (int nt = 0; nt < 8; nt++) {
                unsigned b[2];
                b[0] = Vu[(ks * 8 + t) * VST + nt * 8 + g];
                b[1] = Vu[(ks * 8 + t + 4) * VST + nt * 8 + g];
                mma8(o[nt], a, b);
            }
        }
    }

    // finalize + write [B,N,H*D]
    const int bb = bh >> 3, h = bh & 7;
    #pragma unroll
    for (int half = 0; half < 2; half++) {
        float inv = 1.0f / l_i[half];
        int n = q0 + w16 + g + half * 8;
        float* dst = g_ao + ((size_t)(bb * SEQ + n)) * INNER + h * HDIM;
        #pragma unroll
        for (int nt = 0; nt < 8; nt++) {
            float2 v2;
            v2.x = o[nt][half * 2]     * inv;
            v2.y = o[nt][half * 2 + 1] * inv;
            *(float2*)&dst[nt * 8 + t * 2] = v2;
        }
    }
}

// ---------------------------------------------------------------------------
// Kernel 3: output projection  out = AO @ Wproj + b
// ---------------------------------------------------------------------------
__global__ __launch_bounds__(256) void proj_gemm_kernel(
    const float* __restrict__ W,     // [512, 1024]
    const float* __restrict__ bias,  // [1024]
    float* __restrict__ out)         // [8192, 1024]
{
    __shared__ float As[128 * AST];
    __shared__ float Bs[32 * BST];
    const int tid  = threadIdx.x;
    const int lane = tid & 31, warp = tid >> 5;
    const int wm = (warp >> 2) * 64, wn = (warp & 3) * 32;
    const int g = lane >> 2, t = lane & 3;
    const int row0 = blockIdx.y * 128;
    const int col0 = blockIdx.x * 128;

    float acc[4][4][4];
    #pragma unroll
    for (int mt = 0; mt < 4; mt++)
        #pragma unroll
        for (int nt = 0; nt < 4; nt++)
            #pragma unroll
            for (int r = 0; r < 4; r++) acc[mt][nt][r] = 0.f;

    gemm_mainloop<INNER>(g_ao, INNER, W, EMBED, acc, As, Bs, row0, col0);

    #pragma unroll
    for (int mt = 0; mt < 4; mt++) {
        #pragma unroll
        for (int half = 0; half < 2; half++) {
            int m = row0 + wm + mt * 16 + g + half * 8;
            #pragma unroll
            for (int nt = 0; nt < 4; nt++) {
                int n = col0 + wn + nt * 8 + t * 2;
                float2 v2;
                v2.x = acc[mt][nt][half * 2]     + bias[n];
                v2.y = acc[mt][nt][half * 2 + 1] + bias[n + 1];
                *(float2*)&out[(size_t)m * EMBED + n] = v2;
            }
        }
    }
}

// ---------------------------------------------------------------------------
extern "C" void kernel_launch(void* const* d_in, const int* in_sizes, int n_in,
                              void* d_out, int out_size)
{
    const float* X     = (const float*)d_in[0];
    const float* Wqkv  = (const float*)d_in[1];
    const float* Bqkv  = (const float*)d_in[2];
    const float* Wproj = (const float*)d_in[3];
    const float* Bproj = (const float*)d_in[4];
    float* out = (float*)d_out;

    cudaFuncSetAttribute(attn_kernel,
                         cudaFuncAttributeMaxDynamicSharedMemorySize,
                         ATT_SMEM_BYTES);

    qkv_gemm_kernel<<<dim3(QKVN / 128, MROWS / 128), 256>>>(X, Wqkv, Bqkv);
    attn_kernel<<<dim3(SEQ / 64, BATCH * NHEAD), 128, ATT_SMEM_BYTES>>>();
    proj_gemm_kernel<<<dim3(EMBED / 128, MROWS / 128), 256>>>(Wproj, Bproj, out);
}